// round 16
// baseline (speedup 1.0000x reference)
#include <cuda_runtime.h>
#include <cuda_bf16.h>
#include <cuda_fp16.h>
#include <cstdint>

#define B_SZ     2
#define N_IN     50000
#define N_OUT    12500
#define NNZ      500000
#define IN_C     256
#define OUT_C    256
#define M_ROWS   (B_SZ * N_OUT)   // 25000
#define CAP      128               // padded bucket capacity per row (mean 40)
#define WSCALE   4096.0f           // exact power of 2; keeps W in fp16 normal range
#define WINV     (1.0f / 4096.0f)

// ---------------- scratch (device globals; no allocation allowed) ------------
__device__ int    g_counts[N_OUT];
__device__ float2 g_epad[(size_t)N_OUT * CAP];          // padded edge buckets
__device__ __half g_xh[(size_t)B_SZ * N_IN * IN_C];     // x in fp16 (51.2 MB)
__device__ __half g_axf[(size_t)M_ROWS * IN_C];         // AX in fp16 (12.8 MB)
__device__ __half g_wf[(size_t)OUT_C * IN_C];           // W^T * 4096, fp16: [n][k]

// ---------------- bucket build ------------------------------------------------
__global__ void k_fill_pad(const int* __restrict__ rows,
                           const int* __restrict__ cols,
                           const float* __restrict__ vals) {
    int e = blockIdx.x * blockDim.x + threadIdx.x;
    if (e < NNZ) {
        int r = rows[e];
        int p = atomicAdd(&g_counts[r], 1);
        if (p > CAP - 1) p = CAP - 1;   // statistically unreachable; bounds safety
        float2 ed;
        ed.x = __int_as_float(cols[e]);
        ed.y = vals[e];
        g_epad[(size_t)r * CAP + p] = ed;
    }
}

// ---------------- x -> fp16 streaming conversion (16 floats/thread) ----------
__global__ __launch_bounds__(256) void k_xhalf(const float4* __restrict__ x4) {
    size_t i = (size_t)blockIdx.x * blockDim.x + threadIdx.x;
    float4 a0 = x4[4 * i];
    float4 a1 = x4[4 * i + 1];
    float4 a2 = x4[4 * i + 2];
    float4 a3 = x4[4 * i + 3];
    __half2 h0 = __floats2half2_rn(a0.x, a0.y);
    __half2 h1 = __floats2half2_rn(a0.z, a0.w);
    __half2 h2 = __floats2half2_rn(a1.x, a1.y);
    __half2 h3 = __floats2half2_rn(a1.z, a1.w);
    __half2 h4 = __floats2half2_rn(a2.x, a2.y);
    __half2 h5 = __floats2half2_rn(a2.z, a2.w);
    __half2 h6 = __floats2half2_rn(a3.x, a3.y);
    __half2 h7 = __floats2half2_rn(a3.z, a3.w);
    uint4 o0, o1;
    o0.x = *reinterpret_cast<uint32_t*>(&h0);
    o0.y = *reinterpret_cast<uint32_t*>(&h1);
    o0.z = *reinterpret_cast<uint32_t*>(&h2);
    o0.w = *reinterpret_cast<uint32_t*>(&h3);
    o1.x = *reinterpret_cast<uint32_t*>(&h4);
    o1.y = *reinterpret_cast<uint32_t*>(&h5);
    o1.z = *reinterpret_cast<uint32_t*>(&h6);
    o1.w = *reinterpret_cast<uint32_t*>(&h7);
    *reinterpret_cast<uint4*>(&g_xh[i * 16])     = o0;
    *reinterpret_cast<uint4*>(&g_xh[i * 16 + 8]) = o1;
}

// ---------------- W split/transpose: g_wf[n][k] = fp16(W[k][n] * 4096) -------
__global__ void k_wsplit(const float* __restrict__ W) {
    int idx = blockIdx.x * blockDim.x + threadIdx.x;
    if (idx < IN_C * OUT_C) {
        int k = idx >> 8;
        int n = idx & 255;
        g_wf[(size_t)n * IN_C + k] = __float2half(W[idx] * WSCALE);
    }
}

// ---------------- SpMM v8: one (row,batch) per block, light regs, fp16 -------
// 256 threads = 8 edge-slots x 32 ch-groups (8 halves); one uint4 gather/edge,
// 2-edge unroll (32 B in flight/thread), 4 float4 accumulators. R7 shape.
__device__ __forceinline__ void fma8(float4& a, float4& b, float s, const uint4& h) {
    float2 f0 = __half22float2(*reinterpret_cast<const __half2*>(&h.x));
    float2 f1 = __half22float2(*reinterpret_cast<const __half2*>(&h.y));
    float2 f2 = __half22float2(*reinterpret_cast<const __half2*>(&h.z));
    float2 f3 = __half22float2(*reinterpret_cast<const __half2*>(&h.w));
    a.x = fmaf(s, f0.x, a.x);
    a.y = fmaf(s, f0.y, a.y);
    a.z = fmaf(s, f1.x, a.z);
    a.w = fmaf(s, f1.y, a.w);
    b.x = fmaf(s, f2.x, b.x);
    b.y = fmaf(s, f2.y, b.y);
    b.z = fmaf(s, f3.x, b.z);
    b.w = fmaf(s, f3.y, b.w);
}

__global__ __launch_bounds__(256) void k_spmm() {
    int row   = blockIdx.x;
    int b     = blockIdx.y;
    int tid   = threadIdx.x;
    int eslot = tid >> 5;          // 0..7
    int cg    = tid & 31;          // channel group (8 halves = 16 B)

    __shared__ float4 sred[2][8][32];   // [half(lo4/hi4)][slot][cg]

    int cnt = g_counts[row];
    if (cnt > CAP) cnt = CAP;
    const float2* __restrict__ ep = g_epad + (size_t)row * CAP;
    const __half* __restrict__ xb = g_xh + (size_t)b * N_IN * IN_C + cg * 8;

    float4 a0 = make_float4(0.f, 0.f, 0.f, 0.f);
    float4 b0 = a0, a1 = a0, b1 = a0;   // sets 0/1, (lo4, hi4)

    int j = eslot;
    for (; j + 8 < cnt; j += 16) {
        float2 e0 = ep[j];
        float2 e1 = ep[j + 8];
        size_t o0 = (size_t)__float_as_int(e0.x) * IN_C;
        size_t o1 = (size_t)__float_as_int(e1.x) * IN_C;
        uint4 h0 = *reinterpret_cast<const uint4*>(xb + o0);
        uint4 h1 = *reinterpret_cast<const uint4*>(xb + o1);
        fma8(a0, b0, e0.y, h0);
        fma8(a1, b1, e1.y, h1);
    }
    if (j < cnt) {
        float2 e0 = ep[j];
        size_t o0 = (size_t)__float_as_int(e0.x) * IN_C;
        uint4 h0 = *reinterpret_cast<const uint4*>(xb + o0);
        fma8(a0, b0, e0.y, h0);
    }
    a0.x += a1.x; a0.y += a1.y; a0.z += a1.z; a0.w += a1.w;
    b0.x += b1.x; b0.y += b1.y; b0.z += b1.z; b0.w += b1.w;

    sred[0][eslot][cg] = a0;
    sred[1][eslot][cg] = b0;
    __syncthreads();

    // final: 256 threads, one output channel each: ch = cg2*8 + ch_in
    int cg2 = tid >> 3;            // 0..31
    int ch  = tid & 7;             // 0..7
    int hsel = ch >> 2;
    int lch  = ch & 3;
    const float* src = reinterpret_cast<const float*>(&sred[hsel][0][0]) + cg2 * 4 + lch;
    float v = 0.f;
#pragma unroll
    for (int e = 0; e < 8; e++) v += src[e * 128];
    size_t ofs = ((size_t)b * N_OUT + row) * IN_C + cg2 * 8 + ch;
    g_axf[ofs] = __float2half(v);
}

// ---------------- fp16 MMA GEMM, double-buffered smem + ldmatrix -------------
#define GBM 128
#define GBN 64
#define GBK 32
#define APAD 40   // 80B row stride: conflict-free ldmatrix
#define NCHUNK (IN_C / GBK)   // 8

#define OFF_A 0
#define OFF_B (GBM * APAD)                       // 5120
#define BUF_ELEMS (GBM * APAD + GBN * APAD)      // 7680
#define SMEM_BYTES (2 * BUF_ELEMS * 2)           // 30720

#define MMA_F16(c, a0, a1, a2, a3, b0, b1)                                    \
    asm volatile(                                                             \
        "mma.sync.aligned.m16n8k16.row.col.f32.f16.f16.f32 "                  \
        "{%0,%1,%2,%3},{%4,%5,%6,%7},{%8,%9},{%0,%1,%2,%3};"                  \
        : "+f"((c)[0]), "+f"((c)[1]), "+f"((c)[2]), "+f"((c)[3])              \
        : "r"(a0), "r"(a1), "r"(a2), "r"(a3), "r"(b0), "r"(b1))

#define LDSM_X4(r, addr)                                                      \
    asm volatile("ldmatrix.sync.aligned.m8n8.x4.shared.b16 {%0,%1,%2,%3}, [%4];" \
        : "=r"((r)[0]), "=r"((r)[1]), "=r"((r)[2]), "=r"((r)[3]) : "r"(addr))

__global__ __launch_bounds__(256) void k_gemm_mma(const float* __restrict__ bias,
                                                  float* __restrict__ C) {
    extern __shared__ __half smg[];

    int tid  = threadIdx.x;
    int wid  = tid >> 5;
    int lane = tid & 31;
    int gid  = lane >> 2;
    int tig  = lane & 3;

    int m0 = blockIdx.y * GBM;
    int n0 = blockIdx.x * GBN;
    int warp_m = (wid >> 1) * 32;
    int warp_n = (wid & 1) * 32;

    int ld_row = (lane & 7) | (((lane >> 3) & 1) << 3);   // 0..15
    int ld_k   = (lane >> 4) << 3;                        // 0 or 8

    uint32_t u0 = (uint32_t)__cvta_generic_to_shared(&smg[0]);

    float acc[2][4][4];
#pragma unroll
    for (int i = 0; i < 2; i++)
#pragma unroll
        for (int j = 0; j < 4; j++)
#pragma unroll
            for (int k = 0; k < 4; k++) acc[i][j][k] = 0.f;

    int a_r = tid >> 2;
    int a_c = (tid & 3) * 8;
    int b_r = tid >> 2;
    int b_c = (tid & 3) * 8;

    const uint4 z4 = make_uint4(0u, 0u, 0u, 0u);
    uint4 pa[2], pb;

    int gr0 = m0 + a_r;
    int gr1 = m0 + a_r + 64;
    bool ok0 = (gr0 < M_ROWS);
    bool ok1 = (gr1 < M_ROWS);
    const __half* pA0 = &g_axf[(size_t)gr0 * IN_C + a_c];
    const __half* pA1 = &g_axf[(size_t)gr1 * IN_C + a_c];
    const __half* pB  = &g_wf[(size_t)(n0 + b_r) * IN_C + b_c];

    pa[0] = ok0 ? *reinterpret_cast<const uint4*>(pA0) : z4;
    pa[1] = ok1 ? *reinterpret_cast<const uint4*>(pA1) : z4;
    pb    = *reinterpret_cast<const uint4*>(pB);
    {
        __half* base = smg;
        *reinterpret_cast<uint4*>(base + OFF_A + a_r * APAD + a_c)        = pa[0];
        *reinterpret_cast<uint4*>(base + OFF_A + (a_r + 64) * APAD + a_c) = pa[1];
        *reinterpret_cast<uint4*>(base + OFF_B + b_r * APAD + b_c)        = pb;
    }
    __syncthreads();

    for (int kc = 0; kc < NCHUNK; kc++) {
        int cur = kc & 1;
        int nxt = cur ^ 1;
        uint32_t ubase = u0 + (uint32_t)(cur * BUF_ELEMS) * 2;

        if (kc + 1 < NCHUNK) {
            int kb = (kc + 1) * GBK;
            pa[0] = ok0 ? *reinterpret_cast<const uint4*>(pA0 + kb) : z4;
            pa[1] = ok1 ? *reinterpret_cast<const uint4*>(pA1 + kb) : z4;
            pb    = *reinterpret_cast<const uint4*>(pB + kb);
        }

#pragma unroll
        for (int ks = 0; ks < GBK / 16; ks++) {
            int kk = ks * 16;
            uint32_t af[2][4];
#pragma unroll
            for (int mf = 0; mf < 2; mf++) {
                uint32_t offA = (uint32_t)((warp_m + mf * 16 + ld_row) * APAD + kk + ld_k) * 2;
                LDSM_X4(af[mf], ubase + OFF_A * 2 + offA);
            }
            uint32_t bf[2][4];
#pragma unroll
            for (int p = 0; p < 2; p++) {
                uint32_t offB = (uint32_t)((warp_n + p * 16 + ld_row) * APAD + kk + ld_k) * 2;
                LDSM_X4(bf[p], ubase + OFF_B * 2 + offB);
            }
#pragma unroll
            for (int nf = 0; nf < 4; nf++) {
                int p = nf >> 1;
                int s = nf & 1;
                uint32_t b0 = bf[p][s], b1 = bf[p][s + 2];
#pragma unroll
                for (int mf = 0; mf < 2; mf++) {
                    MMA_F16(acc[mf][nf], af[mf][0], af[mf][1], af[mf][2], af[mf][3], b0, b1);
                }
            }
        }

        if (kc + 1 < NCHUNK) {
            __half* base = smg + nxt * BUF_ELEMS;
            *reinterpret_cast<uint4*>(base + OFF_A + a_r * APAD + a_c)        = pa[0];
            *reinterpret_cast<uint4*>(base + OFF_A + (a_r + 64) * APAD + a_c) = pa[1];
            *reinterpret_cast<uint4*>(base + OFF_B + b_r * APAD + b_c)        = pb;
        }
        __syncthreads();
    }

#pragma unroll
    for (int mf = 0; mf < 2; mf++) {
        int row0 = m0 + warp_m + mf * 16 + gid;
#pragma unroll
        for (int half = 0; half < 2; half++) {
            int row = row0 + half * 8;
            if (row >= M_ROWS) continue;
            int brow = (row >= N_OUT) ? row - N_OUT : row;
#pragma unroll
            for (int nf = 0; nf < 4; nf++) {
                int col = n0 + warp_n + nf * 8 + tig * 2;
                float2 bb = *reinterpret_cast<const float2*>(bias + (size_t)brow * OUT_C + col);
                float2 o;
                o.x = acc[mf][nf][half * 2 + 0] * WINV + bb.x;
                o.y = acc[mf][nf][half * 2 + 1] * WINV + bb.y;
                *reinterpret_cast<float2*>(C + (size_t)row * OUT_C + col) = o;
            }
        }
    }
}

// ---------------- launch -----------------------------------------------------
extern "C" void kernel_launch(void* const* d_in, const int* in_sizes, int n_in,
                              void* d_out, int out_size) {
    const float* x      = (const float*)d_in[0];
    const int*   rows   = (const int*)d_in[1];
    const int*   cols   = (const int*)d_in[2];
    const float* vals   = (const float*)d_in[3];
    const float* weight = (const float*)d_in[4];
    const float* bias   = (const float*)d_in[5];
    float*       out    = (float*)d_out;

    cudaFuncSetAttribute(k_gemm_mma, cudaFuncAttributeMaxDynamicSharedMemorySize, SMEM_BYTES);

    void* p_counts = nullptr;
    cudaGetSymbolAddress(&p_counts, g_counts);
    cudaMemsetAsync(p_counts, 0, N_OUT * sizeof(int));

    k_xhalf<<<(B_SZ * N_IN * IN_C / 16 + 255) / 256, 256>>>((const float4*)x);
    k_fill_pad<<<(NNZ + 255) / 256, 256>>>(rows, cols, vals);
    k_wsplit<<<(IN_C * OUT_C + 255) / 256, 256>>>(weight);

    dim3 sgrid(N_OUT, B_SZ);
    k_spmm<<<sgrid, 256>>>();

    dim3 ggrid(OUT_C / GBN, (M_ROWS + GBM - 1) / GBM);
    k_gemm_mma<<<ggrid, 256, SMEM_BYTES>>>(bias, out);
}

// round 17
// speedup vs baseline: 1.0489x; 1.0489x over previous
#include <cuda_runtime.h>
#include <cuda_bf16.h>
#include <cuda_fp16.h>
#include <cstdint>

#define B_SZ     2
#define N_IN     50000
#define N_OUT    12500
#define NNZ      500000
#define IN_C     256
#define OUT_C    256
#define M_ROWS   (B_SZ * N_OUT)   // 25000
#define CAP      128               // padded bucket capacity per row (mean 40)
#define WSCALE   4096.0f           // exact power of 2; keeps W in fp16 normal range
#define WINV     (1.0f / 4096.0f)

// ---------------- scratch (device globals; no allocation allowed) ------------
__device__ int    g_counts[N_OUT];
__device__ float2 g_epad[(size_t)N_OUT * CAP];          // padded edge buckets
__device__ __half g_xh[(size_t)B_SZ * N_IN * IN_C];     // x in fp16 (51.2 MB)
__device__ __half g_axf[(size_t)M_ROWS * IN_C];         // AX in fp16 (12.8 MB)
__device__ __half g_wf[(size_t)OUT_C * IN_C];           // W^T * 4096, fp16: [n][k]

// ---------------- bucket build ------------------------------------------------
__global__ void k_fill_pad(const int* __restrict__ rows,
                           const int* __restrict__ cols,
                           const float* __restrict__ vals) {
    int e = blockIdx.x * blockDim.x + threadIdx.x;
    if (e < NNZ) {
        int r = rows[e];
        int p = atomicAdd(&g_counts[r], 1);
        if (p > CAP - 1) p = CAP - 1;   // statistically unreachable; bounds safety
        float2 ed;
        ed.x = __int_as_float(cols[e]);
        ed.y = vals[e];
        g_epad[(size_t)r * CAP + p] = ed;
    }
}

// ---------------- x -> fp16 streaming conversion (16 floats/thread) ----------
__global__ __launch_bounds__(256) void k_xhalf(const float4* __restrict__ x4) {
    size_t i = (size_t)blockIdx.x * blockDim.x + threadIdx.x;
    float4 a0 = x4[4 * i];
    float4 a1 = x4[4 * i + 1];
    float4 a2 = x4[4 * i + 2];
    float4 a3 = x4[4 * i + 3];
    __half2 h0 = __floats2half2_rn(a0.x, a0.y);
    __half2 h1 = __floats2half2_rn(a0.z, a0.w);
    __half2 h2 = __floats2half2_rn(a1.x, a1.y);
    __half2 h3 = __floats2half2_rn(a1.z, a1.w);
    __half2 h4 = __floats2half2_rn(a2.x, a2.y);
    __half2 h5 = __floats2half2_rn(a2.z, a2.w);
    __half2 h6 = __floats2half2_rn(a3.x, a3.y);
    __half2 h7 = __floats2half2_rn(a3.z, a3.w);
    uint4 o0, o1;
    o0.x = *reinterpret_cast<uint32_t*>(&h0);
    o0.y = *reinterpret_cast<uint32_t*>(&h1);
    o0.z = *reinterpret_cast<uint32_t*>(&h2);
    o0.w = *reinterpret_cast<uint32_t*>(&h3);
    o1.x = *reinterpret_cast<uint32_t*>(&h4);
    o1.y = *reinterpret_cast<uint32_t*>(&h5);
    o1.z = *reinterpret_cast<uint32_t*>(&h6);
    o1.w = *reinterpret_cast<uint32_t*>(&h7);
    *reinterpret_cast<uint4*>(&g_xh[i * 16])     = o0;
    *reinterpret_cast<uint4*>(&g_xh[i * 16 + 8]) = o1;
}

// ---------------- W split/transpose: g_wf[n][k] = fp16(W[k][n] * 4096) -------
__global__ void k_wsplit(const float* __restrict__ W) {
    int idx = blockIdx.x * blockDim.x + threadIdx.x;
    if (idx < IN_C * OUT_C) {
        int k = idx >> 8;
        int n = idx & 255;
        g_wf[(size_t)n * IN_C + k] = __float2half(W[idx] * WSCALE);
    }
}

// ---------------- SpMM v9: register edge cache + shfl, fused batches ---------
// grid = N_OUT, 256 threads = 8 warps (edge slots) x 32 lanes (ch groups).
// Warp w owns edges {w, w+8, ...}; lane l preloads edge w+8l ONCE, then the
// gather loop reads (col,val) via __shfl_sync — no memory on the chain.
__device__ __forceinline__ void fma8(float4& a, float4& b, float s, const uint4& h) {
    float2 f0 = __half22float2(*reinterpret_cast<const __half2*>(&h.x));
    float2 f1 = __half22float2(*reinterpret_cast<const __half2*>(&h.y));
    float2 f2 = __half22float2(*reinterpret_cast<const __half2*>(&h.z));
    float2 f3 = __half22float2(*reinterpret_cast<const __half2*>(&h.w));
    a.x = fmaf(s, f0.x, a.x);
    a.y = fmaf(s, f0.y, a.y);
    a.z = fmaf(s, f1.x, a.z);
    a.w = fmaf(s, f1.y, a.w);
    b.x = fmaf(s, f2.x, b.x);
    b.y = fmaf(s, f2.y, b.y);
    b.z = fmaf(s, f3.x, b.z);
    b.w = fmaf(s, f3.y, b.w);
}

__global__ __launch_bounds__(256) void k_spmm() {
    int row  = blockIdx.x;
    int tid  = threadIdx.x;
    int w    = tid >> 5;           // warp = edge slot 0..7
    int lane = tid & 31;           // channel group (8 halves = 16 B)

    __shared__ float4 sred[2][2][8][32];   // [batch][half(lo4/hi4)][slot][cg]

    int cnt = g_counts[row];
    if (cnt > CAP) cnt = CAP;

    // per-lane edge preload: lane l (<16) holds edge (w + 8*l)
    int   ecol = 0;
    float eval = 0.f;
    int eidx = w + (lane << 3);
    if (lane < 16 && eidx < cnt) {
        float2 e = g_epad[(size_t)row * CAP + eidx];
        ecol = __float_as_int(e.x);
        eval = e.y;
    }

    const __half* __restrict__ xb0 = g_xh + (size_t)lane * 8;
    const __half* __restrict__ xb1 = g_xh + (size_t)N_IN * IN_C + lane * 8;

    // number of edges this warp owns (warp-uniform)
    int ew = (cnt > w) ? (((cnt - 1 - w) >> 3) + 1) : 0;

    float4 p0 = make_float4(0.f, 0.f, 0.f, 0.f);
    float4 q0 = p0, p1 = p0, q1 = p0;   // batch0: (lo,hi) x 2 sets
    float4 r0 = p0, s0 = p0, r1 = p0, s1 = p0;   // batch1

    int i = 0;
    for (; i + 1 < ew; i += 2) {
        int   cA = __shfl_sync(0xffffffffu, ecol, i);
        float vA = __shfl_sync(0xffffffffu, eval, i);
        int   cB = __shfl_sync(0xffffffffu, ecol, i + 1);
        float vB = __shfl_sync(0xffffffffu, eval, i + 1);
        size_t oA = (size_t)cA * IN_C;
        size_t oB = (size_t)cB * IN_C;
        uint4 hA0 = *reinterpret_cast<const uint4*>(xb0 + oA);
        uint4 hA1 = *reinterpret_cast<const uint4*>(xb1 + oA);
        uint4 hB0 = *reinterpret_cast<const uint4*>(xb0 + oB);
        uint4 hB1 = *reinterpret_cast<const uint4*>(xb1 + oB);
        fma8(p0, q0, vA, hA0);
        fma8(r0, s0, vA, hA1);
        fma8(p1, q1, vB, hB0);
        fma8(r1, s1, vB, hB1);
    }
    if (i < ew) {
        int   cA = __shfl_sync(0xffffffffu, ecol, i);
        float vA = __shfl_sync(0xffffffffu, eval, i);
        size_t oA = (size_t)cA * IN_C;
        uint4 hA0 = *reinterpret_cast<const uint4*>(xb0 + oA);
        uint4 hA1 = *reinterpret_cast<const uint4*>(xb1 + oA);
        fma8(p0, q0, vA, hA0);
        fma8(r0, s0, vA, hA1);
    }
    p0.x += p1.x; p0.y += p1.y; p0.z += p1.z; p0.w += p1.w;
    q0.x += q1.x; q0.y += q1.y; q0.z += q1.z; q0.w += q1.w;
    r0.x += r1.x; r0.y += r1.y; r0.z += r1.z; r0.w += r1.w;
    s0.x += s1.x; s0.y += s1.y; s0.z += s1.z; s0.w += s1.w;

    sred[0][0][w][lane] = p0;
    sred[0][1][w][lane] = q0;
    sred[1][0][w][lane] = r0;
    sred[1][1][w][lane] = s0;
    __syncthreads();

    int cg2 = tid >> 3;            // 0..31
    int ch  = tid & 7;             // 0..7
    int hsel = ch >> 2;
    int lch  = ch & 3;
#pragma unroll
    for (int b = 0; b < 2; b++) {
        const float* src = reinterpret_cast<const float*>(&sred[b][hsel][0][0]) + cg2 * 4 + lch;
        float v = 0.f;
#pragma unroll
        for (int e = 0; e < 8; e++) v += src[e * 128];
        size_t ofs = ((size_t)b * N_OUT + row) * IN_C + cg2 * 8 + ch;
        g_axf[ofs] = __float2half(v);
    }
}

// ---------------- fp16 MMA GEMM, double-buffered smem + ldmatrix -------------
#define GBM 128
#define GBN 64
#define GBK 32
#define APAD 40   // 80B row stride: conflict-free ldmatrix
#define NCHUNK (IN_C / GBK)   // 8

#define OFF_A 0
#define OFF_B (GBM * APAD)                       // 5120
#define BUF_ELEMS (GBM * APAD + GBN * APAD)      // 7680
#define SMEM_BYTES (2 * BUF_ELEMS * 2)           // 30720

#define MMA_F16(c, a0, a1, a2, a3, b0, b1)                                    \
    asm volatile(                                                             \
        "mma.sync.aligned.m16n8k16.row.col.f32.f16.f16.f32 "                  \
        "{%0,%1,%2,%3},{%4,%5,%6,%7},{%8,%9},{%0,%1,%2,%3};"                  \
        : "+f"((c)[0]), "+f"((c)[1]), "+f"((c)[2]), "+f"((c)[3])              \
        : "r"(a0), "r"(a1), "r"(a2), "r"(a3), "r"(b0), "r"(b1))

#define LDSM_X4(r, addr)                                                      \
    asm volatile("ldmatrix.sync.aligned.m8n8.x4.shared.b16 {%0,%1,%2,%3}, [%4];" \
        : "=r"((r)[0]), "=r"((r)[1]), "=r"((r)[2]), "=r"((r)[3]) : "r"(addr))

__global__ __launch_bounds__(256) void k_gemm_mma(const float* __restrict__ bias,
                                                  float* __restrict__ C) {
    extern __shared__ __half smg[];

    int tid  = threadIdx.x;
    int wid  = tid >> 5;
    int lane = tid & 31;
    int gid  = lane >> 2;
    int tig  = lane & 3;

    int m0 = blockIdx.y * GBM;
    int n0 = blockIdx.x * GBN;
    int warp_m = (wid >> 1) * 32;
    int warp_n = (wid & 1) * 32;

    int ld_row = (lane & 7) | (((lane >> 3) & 1) << 3);   // 0..15
    int ld_k   = (lane >> 4) << 3;                        // 0 or 8

    uint32_t u0 = (uint32_t)__cvta_generic_to_shared(&smg[0]);

    float acc[2][4][4];
#pragma unroll
    for (int i = 0; i < 2; i++)
#pragma unroll
        for (int j = 0; j < 4; j++)
#pragma unroll
            for (int k = 0; k < 4; k++) acc[i][j][k] = 0.f;

    int a_r = tid >> 2;
    int a_c = (tid & 3) * 8;
    int b_r = tid >> 2;
    int b_c = (tid & 3) * 8;

    const uint4 z4 = make_uint4(0u, 0u, 0u, 0u);
    uint4 pa[2], pb;

    int gr0 = m0 + a_r;
    int gr1 = m0 + a_r + 64;
    bool ok0 = (gr0 < M_ROWS);
    bool ok1 = (gr1 < M_ROWS);
    const __half* pA0 = &g_axf[(size_t)gr0 * IN_C + a_c];
    const __half* pA1 = &g_axf[(size_t)gr1 * IN_C + a_c];
    const __half* pB  = &g_wf[(size_t)(n0 + b_r) * IN_C + b_c];

    pa[0] = ok0 ? *reinterpret_cast<const uint4*>(pA0) : z4;
    pa[1] = ok1 ? *reinterpret_cast<const uint4*>(pA1) : z4;
    pb    = *reinterpret_cast<const uint4*>(pB);
    {
        __half* base = smg;
        *reinterpret_cast<uint4*>(base + OFF_A + a_r * APAD + a_c)        = pa[0];
        *reinterpret_cast<uint4*>(base + OFF_A + (a_r + 64) * APAD + a_c) = pa[1];
        *reinterpret_cast<uint4*>(base + OFF_B + b_r * APAD + b_c)        = pb;
    }
    __syncthreads();

    for (int kc = 0; kc < NCHUNK; kc++) {
        int cur = kc & 1;
        int nxt = cur ^ 1;
        uint32_t ubase = u0 + (uint32_t)(cur * BUF_ELEMS) * 2;

        if (kc + 1 < NCHUNK) {
            int kb = (kc + 1) * GBK;
            pa[0] = ok0 ? *reinterpret_cast<const uint4*>(pA0 + kb) : z4;
            pa[1] = ok1 ? *reinterpret_cast<const uint4*>(pA1 + kb) : z4;
            pb    = *reinterpret_cast<const uint4*>(pB + kb);
        }

#pragma unroll
        for (int ks = 0; ks < GBK / 16; ks++) {
            int kk = ks * 16;
            uint32_t af[2][4];
#pragma unroll
            for (int mf = 0; mf < 2; mf++) {
                uint32_t offA = (uint32_t)((warp_m + mf * 16 + ld_row) * APAD + kk + ld_k) * 2;
                LDSM_X4(af[mf], ubase + OFF_A * 2 + offA);
            }
            uint32_t bf[2][4];
#pragma unroll
            for (int p = 0; p < 2; p++) {
                uint32_t offB = (uint32_t)((warp_n + p * 16 + ld_row) * APAD + kk + ld_k) * 2;
                LDSM_X4(bf[p], ubase + OFF_B * 2 + offB);
            }
#pragma unroll
            for (int nf = 0; nf < 4; nf++) {
                int p = nf >> 1;
                int s = nf & 1;
                uint32_t b0 = bf[p][s], b1 = bf[p][s + 2];
#pragma unroll
                for (int mf = 0; mf < 2; mf++) {
                    MMA_F16(acc[mf][nf], af[mf][0], af[mf][1], af[mf][2], af[mf][3], b0, b1);
                }
            }
        }

        if (kc + 1 < NCHUNK) {
            __half* base = smg + nxt * BUF_ELEMS;
            *reinterpret_cast<uint4*>(base + OFF_A + a_r * APAD + a_c)        = pa[0];
            *reinterpret_cast<uint4*>(base + OFF_A + (a_r + 64) * APAD + a_c) = pa[1];
            *reinterpret_cast<uint4*>(base + OFF_B + b_r * APAD + b_c)        = pb;
        }
        __syncthreads();
    }

#pragma unroll
    for (int mf = 0; mf < 2; mf++) {
        int row0 = m0 + warp_m + mf * 16 + gid;
#pragma unroll
        for (int half = 0; half < 2; half++) {
            int row = row0 + half * 8;
            if (row >= M_ROWS) continue;
            int brow = (row >= N_OUT) ? row - N_OUT : row;
#pragma unroll
            for (int nf = 0; nf < 4; nf++) {
                int col = n0 + warp_n + nf * 8 + tig * 2;
                float2 bb = *reinterpret_cast<const float2*>(bias + (size_t)brow * OUT_C + col);
                float2 o;
                o.x = acc[mf][nf][half * 2 + 0] * WINV + bb.x;
                o.y = acc[mf][nf][half * 2 + 1] * WINV + bb.y;
                *reinterpret_cast<float2*>(C + (size_t)row * OUT_C + col) = o;
            }
        }
    }
}

// ---------------- launch -----------------------------------------------------
extern "C" void kernel_launch(void* const* d_in, const int* in_sizes, int n_in,
                              void* d_out, int out_size) {
    const float* x      = (const float*)d_in[0];
    const int*   rows   = (const int*)d_in[1];
    const int*   cols   = (const int*)d_in[2];
    const float* vals   = (const float*)d_in[3];
    const float* weight = (const float*)d_in[4];
    const float* bias   = (const float*)d_in[5];
    float*       out    = (float*)d_out;

    cudaFuncSetAttribute(k_gemm_mma, cudaFuncAttributeMaxDynamicSharedMemorySize, SMEM_BYTES);

    void* p_counts = nullptr;
    cudaGetSymbolAddress(&p_counts, g_counts);
    cudaMemsetAsync(p_counts, 0, N_OUT * sizeof(int));

    k_xhalf<<<(B_SZ * N_IN * IN_C / 16 + 255) / 256, 256>>>((const float4*)x);
    k_fill_pad<<<(NNZ + 255) / 256, 256>>>(rows, cols, vals);
    k_wsplit<<<(IN_C * OUT_C + 255) / 256, 256>>>(weight);

    k_spmm<<<N_OUT, 256>>>();

    dim3 ggrid(OUT_C / GBN, (M_ROWS + GBM - 1) / GBM);
    k_gemm_mma<<<ggrid, 256, SMEM_BYTES>>>(bias, out);
}